// round 14
// baseline (speedup 1.0000x reference)
#include <cuda_runtime.h>
#include <cuda_fp16.h>
#include <cstdint>
#include <cstddef>

// Problem constants
#define TT 32768      // tokens (B*S)
#define DD 512        // model dim
#define FF 2048       // ffn dim
#define EE 8          // experts
#define SLOTS 65536   // TT * K(=2)

#define NPERSIST 304  // 152 SMs x 2 resident CTAs (96KB smem, <=128 regs)

// ---------------------------------------------------------------------------
// Device scratch (allocation-free rule: __device__ globals).
// Referenced ONLY from device code (host use would hit ATS host-shadow zeros).
// ---------------------------------------------------------------------------
__device__ __align__(256) int   g_e0[TT], g_e1[TT];
__device__ __align__(256) float g_w0t[TT], g_w1t[TT];
__device__ __align__(256) int   g_counts[EE];
__device__ __align__(256) int   g_offsets[EE + 1];
__device__ __align__(256) int   g_cursor[EE];
__device__ __align__(256) int   g_tile_e[528], g_tile_r0[528];
__device__ __align__(256) int   g_num_tiles;
__device__ __align__(256) int   g_slot_token[SLOTS];
__device__ __align__(256) float g_slot_w[SLOTS];

// fp16 operand scratch (single precision operands; fp32 accumulate in MMA)
__device__ __align__(256) __half g_X [(size_t)TT * DD];
__device__ __align__(256) __half g_W1[(size_t)EE * DD * FF];
__device__ __align__(256) __half g_W2[(size_t)EE * FF * DD];
__device__ __align__(256) __half g_H [(size_t)SLOTS * FF];

// ---------------------------------------------------------------------------
// PTX helpers
// ---------------------------------------------------------------------------
__device__ __forceinline__ uint32_t smem_u32(const void* p) {
    uint32_t a;
    asm("{ .reg .u64 t; cvta.to.shared.u64 t, %1; cvt.u32.u64 %0, t; }"
        : "=r"(a) : "l"(p));
    return a;
}

__device__ __forceinline__ void cp16(uint32_t s, const void* g, bool valid) {
    int sz = valid ? 16 : 0;
    asm volatile("cp.async.cg.shared.global [%0], [%1], 16, %2;\n"
                 :: "r"(s), "l"(__cvta_generic_to_global(g)), "r"(sz));
}
__device__ __forceinline__ void cp_commit() {
    asm volatile("cp.async.commit_group;\n" ::);
}
__device__ __forceinline__ void cp_wait1() {
    asm volatile("cp.async.wait_group 1;\n" ::);
}

__device__ __forceinline__ void ldsm_x4(uint32_t* r, uint32_t addr) {
    asm volatile("ldmatrix.sync.aligned.m8n8.x4.shared.b16 {%0,%1,%2,%3}, [%4];"
                 : "=r"(r[0]), "=r"(r[1]), "=r"(r[2]), "=r"(r[3]) : "r"(addr));
}
__device__ __forceinline__ void ldsm_x4_t(uint32_t* r, uint32_t addr) {
    asm volatile("ldmatrix.sync.aligned.m8n8.x4.trans.shared.b16 {%0,%1,%2,%3}, [%4];"
                 : "=r"(r[0]), "=r"(r[1]), "=r"(r[2]), "=r"(r[3]) : "r"(addr));
}

__device__ __forceinline__ void mma_f16(float* d, const uint32_t* a,
                                        uint32_t b0, uint32_t b1) {
    asm volatile(
        "mma.sync.aligned.m16n8k16.row.col.f32.f16.f16.f32 "
        "{%0,%1,%2,%3}, {%4,%5,%6,%7}, {%8,%9}, {%0,%1,%2,%3};\n"
        : "+f"(d[0]), "+f"(d[1]), "+f"(d[2]), "+f"(d[3])
        : "r"(a[0]), "r"(a[1]), "r"(a[2]), "r"(a[3]), "r"(b0), "r"(b1));
}

// ---------------------------------------------------------------------------
// Router (+ fused x->fp16 convert): logits = x @ Wr + br ; top-2 ;
// renormalized softmax weights. Each block also converts its own 8 rows of x.
// ---------------------------------------------------------------------------
__global__ void k_router(const float* __restrict__ x,
                         const float* __restrict__ Wr,
                         const float* __restrict__ br) {
    __shared__ float sW[EE * DD];   // transposed: sW[e*512 + d]
    __shared__ float sbr[EE];
    const int tid = threadIdx.x;

    // Fused convert: this block's 8 token rows = 4096 floats = 1024 float4
    {
        size_t base = (size_t)blockIdx.x * 8 * DD;
#pragma unroll
        for (int k = 0; k < 4; k++) {
            size_t i = base + (size_t)(tid + k * 256) * 4;
            float4 v = *reinterpret_cast<const float4*>(x + i);
            __half2 a; a.x = __float2half_rn(v.x); a.y = __float2half_rn(v.y);
            __half2 b; b.x = __float2half_rn(v.z); b.y = __float2half_rn(v.w);
            *reinterpret_cast<__half2*>(g_X + i)     = a;
            *reinterpret_cast<__half2*>(g_X + i + 2) = b;
        }
    }

    for (int i = tid; i < EE * DD; i += 256) {
        int e = i >> 9, d = i & 511;
        sW[i] = Wr[d * EE + e];
    }
    if (tid < EE) sbr[tid] = br[tid];
    __syncthreads();

    const int lane = tid & 31, wid = tid >> 5;
    const int t = blockIdx.x * 8 + wid;
    const float* xr = x + (size_t)t * DD;

    float a[EE];
#pragma unroll
    for (int e = 0; e < EE; e++) a[e] = 0.f;
#pragma unroll
    for (int i = 0; i < 16; i++) {
        float xv = xr[lane + 32 * i];
#pragma unroll
        for (int e = 0; e < EE; e++) a[e] += xv * sW[e * DD + lane + 32 * i];
    }
#pragma unroll
    for (int off = 16; off > 0; off >>= 1) {
#pragma unroll
        for (int e = 0; e < EE; e++)
            a[e] += __shfl_down_sync(0xffffffffu, a[e], off);
    }
    if (lane == 0) {
#pragma unroll
        for (int e = 0; e < EE; e++) a[e] += sbr[e];
        int e0 = 0; float m0 = a[0];
#pragma unroll
        for (int e = 1; e < EE; e++) if (a[e] > m0) { m0 = a[e]; e0 = e; }
        int e1 = -1; float m1 = -1e30f;
#pragma unroll
        for (int e = 0; e < EE; e++)
            if (e != e0 && a[e] > m1) { m1 = a[e]; e1 = e; }
        float d  = expf(m1 - m0);           // m1 <= m0
        float w0 = 1.f / (1.f + d);
        float w1 = d * w0;
        g_e0[t] = e0; g_e1[t] = e1;
        g_w0t[t] = w0; g_w1t[t] = w1;
        atomicAdd(&g_counts[e0], 1);
        atomicAdd(&g_counts[e1], 1);
    }
}

// ---------------------------------------------------------------------------
// Scan + scatter (expert-grouped slot lists, static tile table)
// ---------------------------------------------------------------------------
__global__ void k_scan() {
    int off = 0;
    for (int e = 0; e < EE; e++) {
        g_offsets[e] = off;
        g_cursor[e]  = off;
        off += g_counts[e];
        g_counts[e] = 0;
    }
    g_offsets[EE] = off;   // == SLOTS
    int nt = 0;
    for (int e = 0; e < EE; e++)
        for (int r = g_offsets[e]; r < g_offsets[e + 1]; r += 128) {
            g_tile_e[nt] = e; g_tile_r0[nt] = r; nt++;
        }
    g_num_tiles = nt;
}

// Warp-aggregated scatter: one atomic per (warp, expert) instead of per token.
__global__ void k_scatter() {
    const int t = blockIdx.x * 256 + threadIdx.x;
    const int lane = threadIdx.x & 31;
    const unsigned ltmask = (1u << lane) - 1u;
    const int e0 = g_e0[t], e1 = g_e1[t];
    int p0 = 0, p1 = 0;
#pragma unroll
    for (int e = 0; e < EE; e++) {
        unsigned m0 = __ballot_sync(0xffffffffu, e0 == e);
        unsigned m1 = __ballot_sync(0xffffffffu, e1 == e);
        int cnt = __popc(m0) + __popc(m1);
        if (cnt == 0) continue;                 // uniform across warp
        int leader = __ffs(m0 | m1) - 1;
        int base = 0;
        if (lane == leader) base = atomicAdd(&g_cursor[e], cnt);
        base = __shfl_sync(0xffffffffu, base, leader);
        if (e0 == e) p0 = base + __popc(m0 & ltmask);
        if (e1 == e) p1 = base + __popc(m0) + __popc(m1 & ltmask);
    }
    g_slot_token[p0] = t; g_slot_w[p0] = g_w0t[t];
    g_slot_token[p1] = t; g_slot_w[p1] = g_w1t[t];
}

// ---------------------------------------------------------------------------
// Weight converter (fp32 -> fp16)
// ---------------------------------------------------------------------------
__global__ void k_convert_w(const float* __restrict__ W1,
                            const float* __restrict__ W2) {
    size_t i = ((size_t)blockIdx.x * 256 + threadIdx.x) * 4;
    const size_t W1N = (size_t)EE * DD * FF;
    const float* src; __half* dst; size_t j;
    if (i < W1N) { src = W1; j = i;        dst = g_W1; }
    else         { src = W2; j = i - W1N;  dst = g_W2; }
    float4 v = *reinterpret_cast<const float4*>(src + j);
    __half2 a; a.x = __float2half_rn(v.x); a.y = __float2half_rn(v.y);
    __half2 b; b.x = __float2half_rn(v.z); b.y = __float2half_rn(v.w);
    *reinterpret_cast<__half2*>(dst + j)     = a;
    *reinterpret_cast<__half2*>(dst + j + 2) = b;
}

__global__ void k_zero(float* __restrict__ out) {
    size_t i = ((size_t)blockIdx.x * 256 + threadIdx.x) * 4;
    *reinterpret_cast<float4*>(out + i) = make_float4(0.f, 0.f, 0.f, 0.f);
}

// ---------------------------------------------------------------------------
// PERSISTENT grouped GEMM (grid-stride over work items, no wave quantization).
// MODE 0: H = relu(Xg @ W1[e] + b1[e]) -> fp16 scratch
// MODE 1: out[token] += w * (H @ W2[e] + b2[e])  (hidden REDG atomics)
// Work item w -> (bid = w/NB, n0 = (w%NB)*128); N fast so co-resident items
// share A rows via L2. Tile: BM=128, BN=128, BK=64; 8 warps (4m x 2n).
// 3-stage cp.async pipeline (slot = iter%3), one __syncthreads per k-iter +
// one per tile boundary (protects slots 0/1 from next tile's prefetch).
// ---------------------------------------------------------------------------
constexpr int SMEM_BYTES = 3 * (16384 + 16384);   // 96KB

template <int MODE>
__global__ void __launch_bounds__(256, 2) k_gemm(
    const float* __restrict__ bias, float* __restrict__ out) {
    constexpr int KDIM = MODE ? FF : DD;
    constexpr int NDIM = MODE ? DD : FF;
    constexpr int KT   = KDIM / 64;
    constexpr int NB   = NDIM / 128;      // 16 (MODE0) or 4 (MODE1)

    extern __shared__ char smem[];
    const uint32_t sA0 = smem_u32(smem);          // 3 x 16KB
    const uint32_t sB0 = sA0 + 3 * 16384;         // 3 x 16KB

    const int tid = threadIdx.x;
    const int lane = tid & 31, wid = tid >> 5;
    const int wm = wid >> 1, wn = wid & 1;        // 4m x 2n

    const __half* A = MODE ? g_H  : g_X;
    const __half* B = MODE ? g_W2 : g_W1;

    const int n_work = g_num_tiles * NB;

    for (int w = blockIdx.x; w < n_work; w += gridDim.x) {
        const int bid  = w / NB;
        const int n0   = (w - bid * NB) * 128;
        const int e       = g_tile_e[bid];
        const int row0    = g_tile_r0[bid];
        const int seg_end = g_offsets[e + 1];

        // Hoisted A-row bases (k-invariant per thread within this tile)
        size_t abase[4];
        bool   avalid[4];
#pragma unroll
        for (int i = 0; i < 4; i++) {
            int row = (tid + i * 256) >> 3;
            int rg  = row0 + row;
            avalid[i] = rg < seg_end;
            if (MODE == 0) {
                int tok = avalid[i] ? g_slot_token[rg] : 0;
                abase[i] = (size_t)tok * DD;
            } else {
                abase[i] = (size_t)(avalid[i] ? rg : 0) * FF;
            }
        }

        auto load_stage = [&](int ko, int st) {
            const int k0 = ko * 64;
#pragma unroll
            for (int i = 0; i < 4; i++) {
                int c    = tid + i * 256;
                int row  = c >> 3;
                int kc   = c & 7;
                int phys = (kc ^ row) & 7;
                uint32_t s = sA0 + st * 16384 + row * 128 + phys * 16;
                cp16(s, A + abase[i] + k0 + (kc << 3), avalid[i]);
            }
#pragma unroll
            for (int i = 0; i < 4; i++) {
                int c    = tid + i * 256;
                int kr   = c >> 4;
                int nc   = c & 15;
                int phys = (nc & 8) | ((nc ^ kr) & 7);
                uint32_t s = sB0 + st * 16384 + kr * 256 + phys * 16;
                size_t bidx = (size_t)e * KDIM * NDIM
                            + (size_t)(k0 + kr) * NDIM + n0 + (nc << 3);
                cp16(s, B + bidx, true);
            }
            cp_commit();
        };

        float acc[2][8][4];
#pragma unroll
        for (int a = 0; a < 2; a++)
#pragma unroll
            for (int b = 0; b < 8; b++)
#pragma unroll
                for (int c = 0; c < 4; c++) acc[a][b][c] = 0.f;

        load_stage(0, 0);
        load_stage(1, 1);
        int st = 0;
        for (int ko = 0; ko < KT; ko++) {
            cp_wait1();          // stage ko resident (<=1 group outstanding)
            __syncthreads();     // all warps done with slot (ko-1)%3 too

            int ld = ko + 2;
            if (ld < KT) load_stage(ld, ld % 3);
            else cp_commit();    // empty group keeps wait_group(1) accounting

#pragma unroll
            for (int ks = 0; ks < 4; ks++) {
                uint32_t af[2][4];
#pragma unroll
                for (int mt = 0; mt < 2; mt++) {
                    int r  = wm * 32 + mt * 16 + (lane & 15);
                    int kc = ks * 2 + (lane >> 4);
                    int ph = (kc ^ r) & 7;
                    ldsm_x4(af[mt], sA0 + st * 16384 + r * 128 + ph * 16);
                }
                uint32_t bf[16];
#pragma unroll
                for (int g = 0; g < 4; g++) {
                    int kr = ks * 16 + (lane & 15);
                    int nc = wn * 8 + g * 2 + (lane >> 4);
                    int ph = (nc & 8) | ((nc ^ kr) & 7);
                    ldsm_x4_t(&bf[g * 4], sB0 + st * 16384 + kr * 256 + ph * 16);
                }
#pragma unroll
                for (int mt = 0; mt < 2; mt++)
#pragma unroll
                    for (int nt = 0; nt < 8; nt++) {
                        int idx = (nt >> 1) * 4 + (nt & 1) * 2;
                        mma_f16(acc[mt][nt], af[mt], bf[idx], bf[idx + 1]);
                    }
            }
            st = (st == 2) ? 0 : st + 1;
        }

        // Epilogue
#pragma unroll
        for (int mt = 0; mt < 2; mt++) {
            int rr = wm * 32 + mt * 16 + (lane >> 2);
#pragma unroll
            for (int i = 0; i < 2; i++) {
                int rg = row0 + rr + i * 8;
                if (rg < seg_end) {
                    if (MODE == 0) {
                        size_t base = (size_t)rg * FF;
#pragma unroll
                        for (int nt = 0; nt < 8; nt++) {
                            int col = n0 + wn * 64 + nt * 8 + ((lane & 3) << 1);
                            float v0 = acc[mt][nt][i * 2 + 0] + bias[e * NDIM + col];
                            float v1 = acc[mt][nt][i * 2 + 1] + bias[e * NDIM + col + 1];
                            __half2 hp;
                            hp.x = __float2half_rn(fmaxf(v0, 0.f));
                            hp.y = __float2half_rn(fmaxf(v1, 0.f));
                            *reinterpret_cast<__half2*>(g_H + base + col) = hp;
                        }
                    } else {
                        int tok = g_slot_token[rg];
                        float wgt = g_slot_w[rg];
                        float* orow = out + (size_t)tok * DD;
#pragma unroll
                        for (int nt = 0; nt < 8; nt++) {
                            int col = n0 + wn * 64 + nt * 8 + ((lane & 3) << 1);
                            float v0 = (acc[mt][nt][i * 2 + 0] + bias[e * NDIM + col]) * wgt;
                            float v1 = (acc[mt][nt][i * 2 + 1] + bias[e * NDIM + col + 1]) * wgt;
                            atomicAdd(orow + col, v0);
                            atomicAdd(orow + col + 1, v1);
                        }
                    }
                }
            }
        }
        // Tile boundary: protect pipeline slots 0/1 from next tile's prefetch
        // while slow warps may still be reading the final slots of this tile.
        __syncthreads();
    }
}

// ---------------------------------------------------------------------------
// Launch
// ---------------------------------------------------------------------------
extern "C" void kernel_launch(void* const* d_in, const int* in_sizes, int n_in,
                              void* d_out, int out_size) {
    const float* x  = (const float*)d_in[0];
    const float* Wr = (const float*)d_in[1];
    const float* br = (const float*)d_in[2];
    const float* W1 = (const float*)d_in[3];
    const float* b1 = (const float*)d_in[4];
    const float* W2 = (const float*)d_in[5];
    const float* b2 = (const float*)d_in[6];
    float* out = (float*)d_out;

    cudaFuncSetAttribute(k_gemm<0>, cudaFuncAttributeMaxDynamicSharedMemorySize,
                         SMEM_BYTES);
    cudaFuncSetAttribute(k_gemm<1>, cudaFuncAttributeMaxDynamicSharedMemorySize,
                         SMEM_BYTES);

    k_convert_w<<<(2 * EE * DD * FF / 4) / 256, 256>>>(W1, W2);
    k_router<<<TT / 8, 256>>>(x, Wr, br);
    k_scan<<<1, 1>>>();
    k_scatter<<<TT / 256, 256>>>();

    // GEMM1: 65536 x 2048, K=512 (grouped), persistent
    k_gemm<0><<<NPERSIST, 256, SMEM_BYTES>>>(b1, nullptr);

    k_zero<<<(TT * DD / 4) / 256, 256>>>(out);

    // GEMM2: 65536 x 512, K=2048 (grouped), persistent, hidden atomics
    k_gemm<1><<<NPERSIST, 256, SMEM_BYTES>>>(b2, out);
}

// round 15
// speedup vs baseline: 1.0854x; 1.0854x over previous
#include <cuda_runtime.h>
#include <cuda_fp16.h>
#include <cstdint>
#include <cstddef>

// Problem constants
#define TT 32768      // tokens (B*S)
#define DD 512        // model dim
#define FF 2048       // ffn dim
#define EE 8          // experts
#define SLOTS 65536   // TT * K(=2)

// ---------------------------------------------------------------------------
// Device scratch (allocation-free rule: __device__ globals).
// Referenced ONLY from device code (host use would hit ATS host-shadow zeros).
// ---------------------------------------------------------------------------
__device__ __align__(256) int   g_e0[TT], g_e1[TT];
__device__ __align__(256) float g_w0t[TT], g_w1t[TT];
__device__ __align__(256) int   g_counts[EE];
__device__ __align__(256) int   g_offsets[EE + 1];
__device__ __align__(256) int   g_cursor[EE];
__device__ __align__(256) int   g_tile_e[528], g_tile_r0[528];
__device__ __align__(256) int   g_num_tiles;
__device__ __align__(256) int   g_slot_token[SLOTS];
__device__ __align__(256) float g_slot_w[SLOTS];

// fp16 operand scratch (single precision operands; fp32 accumulate in MMA)
__device__ __align__(256) __half g_X [(size_t)TT * DD];
__device__ __align__(256) __half g_W1[(size_t)EE * DD * FF];
__device__ __align__(256) __half g_W2[(size_t)EE * FF * DD];
__device__ __align__(256) __half g_H [(size_t)SLOTS * FF];

// ---------------------------------------------------------------------------
// PTX helpers
// ---------------------------------------------------------------------------
__device__ __forceinline__ uint32_t smem_u32(const void* p) {
    uint32_t a;
    asm("{ .reg .u64 t; cvta.to.shared.u64 t, %1; cvt.u32.u64 %0, t; }"
        : "=r"(a) : "l"(p));
    return a;
}

__device__ __forceinline__ void cp16(uint32_t s, const void* g, bool valid) {
    int sz = valid ? 16 : 0;
    asm volatile("cp.async.cg.shared.global [%0], [%1], 16, %2;\n"
                 :: "r"(s), "l"(__cvta_generic_to_global(g)), "r"(sz));
}
__device__ __forceinline__ void cp_commit() {
    asm volatile("cp.async.commit_group;\n" ::);
}
__device__ __forceinline__ void cp_wait1() {
    asm volatile("cp.async.wait_group 1;\n" ::);
}

__device__ __forceinline__ void ldsm_x4(uint32_t* r, uint32_t addr) {
    asm volatile("ldmatrix.sync.aligned.m8n8.x4.shared.b16 {%0,%1,%2,%3}, [%4];"
                 : "=r"(r[0]), "=r"(r[1]), "=r"(r[2]), "=r"(r[3]) : "r"(addr));
}
__device__ __forceinline__ void ldsm_x4_t(uint32_t* r, uint32_t addr) {
    asm volatile("ldmatrix.sync.aligned.m8n8.x4.trans.shared.b16 {%0,%1,%2,%3}, [%4];"
                 : "=r"(r[0]), "=r"(r[1]), "=r"(r[2]), "=r"(r[3]) : "r"(addr));
}

__device__ __forceinline__ void mma_f16(float* d, const uint32_t* a,
                                        uint32_t b0, uint32_t b1) {
    asm volatile(
        "mma.sync.aligned.m16n8k16.row.col.f32.f16.f16.f32 "
        "{%0,%1,%2,%3}, {%4,%5,%6,%7}, {%8,%9}, {%0,%1,%2,%3};\n"
        : "+f"(d[0]), "+f"(d[1]), "+f"(d[2]), "+f"(d[3])
        : "r"(a[0]), "r"(a[1]), "r"(a[2]), "r"(a[3]), "r"(b0), "r"(b1));
}

// ---------------------------------------------------------------------------
// Router (+ fused x->fp16 convert): logits = x @ Wr + br ; top-2 ;
// renormalized softmax weights. Each block also converts its own 8 rows of x.
// ---------------------------------------------------------------------------
__global__ void k_router(const float* __restrict__ x,
                         const float* __restrict__ Wr,
                         const float* __restrict__ br) {
    __shared__ float sW[EE * DD];   // transposed: sW[e*512 + d]
    __shared__ float sbr[EE];
    const int tid = threadIdx.x;

    // Fused convert: this block's 8 token rows = 4096 floats = 1024 float4
    {
        size_t base = (size_t)blockIdx.x * 8 * DD;
#pragma unroll
        for (int k = 0; k < 4; k++) {
            size_t i = base + (size_t)(tid + k * 256) * 4;
            float4 v = *reinterpret_cast<const float4*>(x + i);
            __half2 a; a.x = __float2half_rn(v.x); a.y = __float2half_rn(v.y);
            __half2 b; b.x = __float2half_rn(v.z); b.y = __float2half_rn(v.w);
            *reinterpret_cast<__half2*>(g_X + i)     = a;
            *reinterpret_cast<__half2*>(g_X + i + 2) = b;
        }
    }

    for (int i = tid; i < EE * DD; i += 256) {
        int e = i >> 9, d = i & 511;
        sW[i] = Wr[d * EE + e];
    }
    if (tid < EE) sbr[tid] = br[tid];
    __syncthreads();

    const int lane = tid & 31, wid = tid >> 5;
    const int t = blockIdx.x * 8 + wid;
    const float* xr = x + (size_t)t * DD;

    float a[EE];
#pragma unroll
    for (int e = 0; e < EE; e++) a[e] = 0.f;
#pragma unroll
    for (int i = 0; i < 16; i++) {
        float xv = xr[lane + 32 * i];
#pragma unroll
        for (int e = 0; e < EE; e++) a[e] += xv * sW[e * DD + lane + 32 * i];
    }
#pragma unroll
    for (int off = 16; off > 0; off >>= 1) {
#pragma unroll
        for (int e = 0; e < EE; e++)
            a[e] += __shfl_down_sync(0xffffffffu, a[e], off);
    }
    if (lane == 0) {
#pragma unroll
        for (int e = 0; e < EE; e++) a[e] += sbr[e];
        int e0 = 0; float m0 = a[0];
#pragma unroll
        for (int e = 1; e < EE; e++) if (a[e] > m0) { m0 = a[e]; e0 = e; }
        int e1 = -1; float m1 = -1e30f;
#pragma unroll
        for (int e = 0; e < EE; e++)
            if (e != e0 && a[e] > m1) { m1 = a[e]; e1 = e; }
        float d  = expf(m1 - m0);           // m1 <= m0
        float w0 = 1.f / (1.f + d);
        float w1 = d * w0;
        g_e0[t] = e0; g_e1[t] = e1;
        g_w0t[t] = w0; g_w1t[t] = w1;
        atomicAdd(&g_counts[e0], 1);
        atomicAdd(&g_counts[e1], 1);
    }
}

// ---------------------------------------------------------------------------
// Scan + scatter (expert-grouped slot lists, static tile table)
// ---------------------------------------------------------------------------
__global__ void k_scan() {
    int off = 0;
    for (int e = 0; e < EE; e++) {
        g_offsets[e] = off;
        g_cursor[e]  = off;
        off += g_counts[e];
        g_counts[e] = 0;
    }
    g_offsets[EE] = off;   // == SLOTS
    int nt = 0;
    for (int e = 0; e < EE; e++)
        for (int r = g_offsets[e]; r < g_offsets[e + 1]; r += 128) {
            g_tile_e[nt] = e; g_tile_r0[nt] = r; nt++;
        }
    g_num_tiles = nt;
}

// Warp-aggregated scatter: one atomic per (warp, expert) instead of per token.
// (Measured: 14.5us -> 10.9us vs per-token atomics.)
__global__ void k_scatter() {
    const int t = blockIdx.x * 256 + threadIdx.x;
    const int lane = threadIdx.x & 31;
    const unsigned ltmask = (1u << lane) - 1u;
    const int e0 = g_e0[t], e1 = g_e1[t];
    int p0 = 0, p1 = 0;
#pragma unroll
    for (int e = 0; e < EE; e++) {
        unsigned m0 = __ballot_sync(0xffffffffu, e0 == e);
        unsigned m1 = __ballot_sync(0xffffffffu, e1 == e);
        int cnt = __popc(m0) + __popc(m1);
        if (cnt == 0) continue;                 // uniform across warp
        int leader = __ffs(m0 | m1) - 1;
        int base = 0;
        if (lane == leader) base = atomicAdd(&g_cursor[e], cnt);
        base = __shfl_sync(0xffffffffu, base, leader);
        if (e0 == e) p0 = base + __popc(m0 & ltmask);
        if (e1 == e) p1 = base + __popc(m0) + __popc(m1 & ltmask);
    }
    g_slot_token[p0] = t; g_slot_w[p0] = g_w0t[t];
    g_slot_token[p1] = t; g_slot_w[p1] = g_w1t[t];
}

// ---------------------------------------------------------------------------
// Weight converter (fp32 -> fp16)
// ---------------------------------------------------------------------------
__global__ void k_convert_w(const float* __restrict__ W1,
                            const float* __restrict__ W2) {
    size_t i = ((size_t)blockIdx.x * 256 + threadIdx.x) * 4;
    const size_t W1N = (size_t)EE * DD * FF;
    const float* src; __half* dst; size_t j;
    if (i < W1N) { src = W1; j = i;        dst = g_W1; }
    else         { src = W2; j = i - W1N;  dst = g_W2; }
    float4 v = *reinterpret_cast<const float4*>(src + j);
    __half2 a; a.x = __float2half_rn(v.x); a.y = __float2half_rn(v.y);
    __half2 b; b.x = __float2half_rn(v.z); b.y = __float2half_rn(v.w);
    *reinterpret_cast<__half2*>(dst + j)     = a;
    *reinterpret_cast<__half2*>(dst + j + 2) = b;
}

__global__ void k_zero(float* __restrict__ out) {
    size_t i = ((size_t)blockIdx.x * 256 + threadIdx.x) * 4;
    *reinterpret_cast<float4*>(out + i) = make_float4(0.f, 0.f, 0.f, 0.f);
}

// ---------------------------------------------------------------------------
// Grouped GEMM (round-11 winner config, verbatim).
// MODE 0: H = relu(Xg @ W1[e] + b1[e]) -> fp16 scratch
// MODE 1: out[token] += w * (H @ W2[e] + b2[e])  (hidden REDG atomics)
// Tile: BM=128, BN=128, BK=64. 256 threads = 8 warps (4m x 2n), warp 32x64.
// blockIdx.x = N-block (fast), blockIdx.y = M-tile (A rows shared via L2).
// 3-stage cp.async pipeline (stage = iter % 3), ONE __syncthreads per k-iter,
// 2 CTAs/SM. XOR swizzle on 16B chunks -> conflict-free ldmatrix.
// ---------------------------------------------------------------------------
constexpr int SMEM_BYTES = 3 * (16384 + 16384);   // 96KB

template <int MODE>
__global__ void __launch_bounds__(256, 2) k_gemm(
    const float* __restrict__ bias, float* __restrict__ out) {
    constexpr int KDIM = MODE ? FF : DD;
    constexpr int NDIM = MODE ? DD : FF;
    constexpr int KT   = KDIM / 64;

    const int bid = blockIdx.y;           // M-tile (slow axis)
    if (bid >= g_num_tiles) return;
    const int e       = g_tile_e[bid];
    const int row0    = g_tile_r0[bid];
    const int seg_end = g_offsets[e + 1];
    const int n0      = blockIdx.x * 128; // N-block (fast axis)

    extern __shared__ char smem[];
    const uint32_t sA0 = smem_u32(smem);          // 3 x 16KB
    const uint32_t sB0 = sA0 + 3 * 16384;         // 3 x 16KB

    const int tid = threadIdx.x;
    const int lane = tid & 31, wid = tid >> 5;
    const int wm = wid >> 1, wn = wid & 1;        // 4m x 2n

    const __half* A = MODE ? g_H  : g_X;
    const __half* B = MODE ? g_W2 : g_W1;

    // Hoisted A-row bases (rows handled by this thread are k-invariant)
    size_t abase[4];
    bool   avalid[4];
#pragma unroll
    for (int i = 0; i < 4; i++) {
        int row = (tid + i * 256) >> 3;
        int rg  = row0 + row;
        avalid[i] = rg < seg_end;
        if (MODE == 0) {
            int tok = avalid[i] ? g_slot_token[rg] : 0;
            abase[i] = (size_t)tok * DD;
        } else {
            abase[i] = (size_t)(avalid[i] ? rg : 0) * FF;
        }
    }

    auto load_stage = [&](int ko, int st) {
        const int k0 = ko * 64;
        // A: 128 rows x 8 chunks of 16B (128B/row) = 1024 chunks, 4/thread
#pragma unroll
        for (int i = 0; i < 4; i++) {
            int c    = tid + i * 256;
            int row  = c >> 3;
            int kc   = c & 7;
            int phys = (kc ^ row) & 7;
            uint32_t s = sA0 + st * 16384 + row * 128 + phys * 16;
            cp16(s, A + abase[i] + k0 + (kc << 3), avalid[i]);
        }
        // B: 64 k-rows x 16 chunks (128 fp16 = 256B/row) = 1024 chunks, 4/thread
#pragma unroll
        for (int i = 0; i < 4; i++) {
            int c    = tid + i * 256;
            int kr   = c >> 4;
            int nc   = c & 15;
            int phys = (nc & 8) | ((nc ^ kr) & 7);
            uint32_t s = sB0 + st * 16384 + kr * 256 + phys * 16;
            size_t bidx = (size_t)e * KDIM * NDIM + (size_t)(k0 + kr) * NDIM
                        + n0 + (nc << 3);
            cp16(s, B + bidx, true);
        }
        cp_commit();
    };

    float acc[2][8][4];
#pragma unroll
    for (int a = 0; a < 2; a++)
#pragma unroll
        for (int b = 0; b < 8; b++)
#pragma unroll
            for (int c = 0; c < 4; c++) acc[a][b][c] = 0.f;

    load_stage(0, 0);
    load_stage(1, 1);
    int st = 0;
    for (int ko = 0; ko < KT; ko++) {
        cp_wait1();          // stage ko resident (<=1 group outstanding)
        __syncthreads();     // all warps done with slot (ko-1)%3 too

        int ld = ko + 2;
        if (ld < KT) load_stage(ld, ld % 3);
        else cp_commit();    // empty group keeps wait_group(1) accounting

#pragma unroll
        for (int ks = 0; ks < 4; ks++) {
            uint32_t af[2][4];
#pragma unroll
            for (int mt = 0; mt < 2; mt++) {
                int r  = wm * 32 + mt * 16 + (lane & 15);
                int kc = ks * 2 + (lane >> 4);
                int ph = (kc ^ r) & 7;
                ldsm_x4(af[mt], sA0 + st * 16384 + r * 128 + ph * 16);
            }
            uint32_t bf[16];
#pragma unroll
            for (int g = 0; g < 4; g++) {
                int kr = ks * 16 + (lane & 15);
                int nc = wn * 8 + g * 2 + (lane >> 4);
                int ph = (nc & 8) | ((nc ^ kr) & 7);
                ldsm_x4_t(&bf[g * 4], sB0 + st * 16384 + kr * 256 + ph * 16);
            }
#pragma unroll
            for (int mt = 0; mt < 2; mt++)
#pragma unroll
                for (int nt = 0; nt < 8; nt++) {
                    int idx = (nt >> 1) * 4 + (nt & 1) * 2;
                    mma_f16(acc[mt][nt], af[mt], bf[idx], bf[idx + 1]);
                }
        }
        st = (st == 2) ? 0 : st + 1;
    }

    // Epilogue
#pragma unroll
    for (int mt = 0; mt < 2; mt++) {
        int rr = wm * 32 + mt * 16 + (lane >> 2);
#pragma unroll
        for (int i = 0; i < 2; i++) {
            int rg = row0 + rr + i * 8;
            if (rg < seg_end) {
                if (MODE == 0) {
                    size_t base = (size_t)rg * FF;
#pragma unroll
                    for (int nt = 0; nt < 8; nt++) {
                        int col = n0 + wn * 64 + nt * 8 + ((lane & 3) << 1);
                        float v0 = acc[mt][nt][i * 2 + 0] + bias[e * NDIM + col];
                        float v1 = acc[mt][nt][i * 2 + 1] + bias[e * NDIM + col + 1];
                        __half2 hp;
                        hp.x = __float2half_rn(fmaxf(v0, 0.f));
                        hp.y = __float2half_rn(fmaxf(v1, 0.f));
                        *reinterpret_cast<__half2*>(g_H + base + col) = hp;
                    }
                } else {
                    int tok = g_slot_token[rg];
                    float w = g_slot_w[rg];
                    float* orow = out + (size_t)tok * DD;
#pragma unroll
                    for (int nt = 0; nt < 8; nt++) {
                        int col = n0 + wn * 64 + nt * 8 + ((lane & 3) << 1);
                        float v0 = (acc[mt][nt][i * 2 + 0] + bias[e * NDIM + col]) * w;
                        float v1 = (acc[mt][nt][i * 2 + 1] + bias[e * NDIM + col + 1]) * w;
                        atomicAdd(orow + col, v0);
                        atomicAdd(orow + col + 1, v1);
                    }
                }
            }
        }
    }
}

// ---------------------------------------------------------------------------
// Launch
// ---------------------------------------------------------------------------
extern "C" void kernel_launch(void* const* d_in, const int* in_sizes, int n_in,
                              void* d_out, int out_size) {
    const float* x  = (const float*)d_in[0];
    const float* Wr = (const float*)d_in[1];
    const float* br = (const float*)d_in[2];
    const float* W1 = (const float*)d_in[3];
    const float* b1 = (const float*)d_in[4];
    const float* W2 = (const float*)d_in[5];
    const float* b2 = (const float*)d_in[6];
    float* out = (float*)d_out;

    cudaFuncSetAttribute(k_gemm<0>, cudaFuncAttributeMaxDynamicSharedMemorySize,
                         SMEM_BYTES);
    cudaFuncSetAttribute(k_gemm<1>, cudaFuncAttributeMaxDynamicSharedMemorySize,
                         SMEM_BYTES);

    k_convert_w<<<(2 * EE * DD * FF / 4) / 256, 256>>>(W1, W2);
    k_router<<<TT / 8, 256>>>(x, Wr, br);
    k_scan<<<1, 1>>>();
    k_scatter<<<TT / 256, 256>>>();

    // GEMM1: 65536 x 2048, K=512 (grouped by expert)
    k_gemm<0><<<dim3(FF / 128, 520), 256, SMEM_BYTES>>>(b1, nullptr);

    k_zero<<<(TT * DD / 4) / 256, 256>>>(out);

    // GEMM2: 65536 x 512, K=2048 (grouped), hidden REDG atomics
    k_gemm<1><<<dim3(DD / 128, 520), 256, SMEM_BYTES>>>(b2, out);
}

// round 16
// speedup vs baseline: 1.0925x; 1.0065x over previous
#include <cuda_runtime.h>
#include <cuda_fp16.h>
#include <cstdint>
#include <cstddef>

// Problem constants
#define TT 32768      // tokens (B*S)
#define DD 512        // model dim
#define FF 2048       // ffn dim
#define EE 8          // experts
#define SLOTS 65536   // TT * K(=2)

// ---------------------------------------------------------------------------
// Device scratch (allocation-free rule: __device__ globals).
// Referenced ONLY from device code (host use would hit ATS host-shadow zeros).
// ---------------------------------------------------------------------------
__device__ __align__(256) int   g_e0[TT], g_e1[TT];
__device__ __align__(256) float g_w0t[TT], g_w1t[TT];
__device__ __align__(256) int   g_counts[EE];
__device__ __align__(256) int   g_offsets[EE + 1];
__device__ __align__(256) int   g_cursor[EE];
__device__ __align__(256) int   g_tile_e[528], g_tile_r0[528];
__device__ __align__(256) int   g_num_tiles;
__device__ __align__(256) int   g_slot_token[SLOTS];
__device__ __align__(256) float g_slot_w[SLOTS];

// fp16 operand scratch (single precision operands; fp32 accumulate in MMA)
__device__ __align__(256) __half g_X [(size_t)TT * DD];
__device__ __align__(256) __half g_W1[(size_t)EE * DD * FF];
__device__ __align__(256) __half g_W2[(size_t)EE * FF * DD];
__device__ __align__(256) __half g_H [(size_t)SLOTS * FF];

// ---------------------------------------------------------------------------
// PTX helpers
// ---------------------------------------------------------------------------
__device__ __forceinline__ uint32_t smem_u32(const void* p) {
    uint32_t a;
    asm("{ .reg .u64 t; cvta.to.shared.u64 t, %1; cvt.u32.u64 %0, t; }"
        : "=r"(a) : "l"(p));
    return a;
}

__device__ __forceinline__ void cp16(uint32_t s, const void* g, bool valid) {
    int sz = valid ? 16 : 0;
    asm volatile("cp.async.cg.shared.global [%0], [%1], 16, %2;\n"
                 :: "r"(s), "l"(__cvta_generic_to_global(g)), "r"(sz));
}
__device__ __forceinline__ void cp_commit() {
    asm volatile("cp.async.commit_group;\n" ::);
}
__device__ __forceinline__ void cp_wait1() {
    asm volatile("cp.async.wait_group 1;\n" ::);
}

__device__ __forceinline__ void ldsm_x4(uint32_t* r, uint32_t addr) {
    asm volatile("ldmatrix.sync.aligned.m8n8.x4.shared.b16 {%0,%1,%2,%3}, [%4];"
                 : "=r"(r[0]), "=r"(r[1]), "=r"(r[2]), "=r"(r[3]) : "r"(addr));
}
__device__ __forceinline__ void ldsm_x4_t(uint32_t* r, uint32_t addr) {
    asm volatile("ldmatrix.sync.aligned.m8n8.x4.trans.shared.b16 {%0,%1,%2,%3}, [%4];"
                 : "=r"(r[0]), "=r"(r[1]), "=r"(r[2]), "=r"(r[3]) : "r"(addr));
}

__device__ __forceinline__ void mma_f16(float* d, const uint32_t* a,
                                        uint32_t b0, uint32_t b1) {
    asm volatile(
        "mma.sync.aligned.m16n8k16.row.col.f32.f16.f16.f32 "
        "{%0,%1,%2,%3}, {%4,%5,%6,%7}, {%8,%9}, {%0,%1,%2,%3};\n"
        : "+f"(d[0]), "+f"(d[1]), "+f"(d[2]), "+f"(d[3])
        : "r"(a[0]), "r"(a[1]), "r"(a[2]), "r"(a[3]), "r"(b0), "r"(b1));
}

// ---------------------------------------------------------------------------
// Router (+ fused x->fp16 convert): logits = x @ Wr + br ; top-2 ;
// renormalized softmax weights. Each block also converts its own 8 rows of x.
// ---------------------------------------------------------------------------
__global__ void k_router(const float* __restrict__ x,
                         const float* __restrict__ Wr,
                         const float* __restrict__ br) {
    __shared__ float sW[EE * DD];   // transposed: sW[e*512 + d]
    __shared__ float sbr[EE];
    const int tid = threadIdx.x;

    // Fused convert: this block's 8 token rows = 4096 floats = 1024 float4
    {
        size_t base = (size_t)blockIdx.x * 8 * DD;
#pragma unroll
        for (int k = 0; k < 4; k++) {
            size_t i = base + (size_t)(tid + k * 256) * 4;
            float4 v = *reinterpret_cast<const float4*>(x + i);
            __half2 a; a.x = __float2half_rn(v.x); a.y = __float2half_rn(v.y);
            __half2 b; b.x = __float2half_rn(v.z); b.y = __float2half_rn(v.w);
            *reinterpret_cast<__half2*>(g_X + i)     = a;
            *reinterpret_cast<__half2*>(g_X + i + 2) = b;
        }
    }

    for (int i = tid; i < EE * DD; i += 256) {
        int e = i >> 9, d = i & 511;
        sW[i] = Wr[d * EE + e];
    }
    if (tid < EE) sbr[tid] = br[tid];
    __syncthreads();

    const int lane = tid & 31, wid = tid >> 5;
    const int t = blockIdx.x * 8 + wid;
    const float* xr = x + (size_t)t * DD;

    float a[EE];
#pragma unroll
    for (int e = 0; e < EE; e++) a[e] = 0.f;
#pragma unroll
    for (int i = 0; i < 16; i++) {
        float xv = xr[lane + 32 * i];
#pragma unroll
        for (int e = 0; e < EE; e++) a[e] += xv * sW[e * DD + lane + 32 * i];
    }
#pragma unroll
    for (int off = 16; off > 0; off >>= 1) {
#pragma unroll
        for (int e = 0; e < EE; e++)
            a[e] += __shfl_down_sync(0xffffffffu, a[e], off);
    }
    if (lane == 0) {
#pragma unroll
        for (int e = 0; e < EE; e++) a[e] += sbr[e];
        int e0 = 0; float m0 = a[0];
#pragma unroll
        for (int e = 1; e < EE; e++) if (a[e] > m0) { m0 = a[e]; e0 = e; }
        int e1 = -1; float m1 = -1e30f;
#pragma unroll
        for (int e = 0; e < EE; e++)
            if (e != e0 && a[e] > m1) { m1 = a[e]; e1 = e; }
        float d  = expf(m1 - m0);           // m1 <= m0
        float w0 = 1.f / (1.f + d);
        float w1 = d * w0;
        g_e0[t] = e0; g_e1[t] = e1;
        g_w0t[t] = w0; g_w1t[t] = w1;
        atomicAdd(&g_counts[e0], 1);
        atomicAdd(&g_counts[e1], 1);
    }
}

// ---------------------------------------------------------------------------
// Scan + scatter (expert-grouped slot lists, static tile table)
// ---------------------------------------------------------------------------
__global__ void k_scan() {
    int off = 0;
    for (int e = 0; e < EE; e++) {
        g_offsets[e] = off;
        g_cursor[e]  = off;
        off += g_counts[e];
        g_counts[e] = 0;
    }
    g_offsets[EE] = off;   // == SLOTS
    int nt = 0;
    for (int e = 0; e < EE; e++)
        for (int r = g_offsets[e]; r < g_offsets[e + 1]; r += 128) {
            g_tile_e[nt] = e; g_tile_r0[nt] = r; nt++;
        }
    g_num_tiles = nt;
}

// Warp-aggregated scatter: one atomic per (warp, expert) instead of per token.
__global__ void k_scatter() {
    const int t = blockIdx.x * 256 + threadIdx.x;
    const int lane = threadIdx.x & 31;
    const unsigned ltmask = (1u << lane) - 1u;
    const int e0 = g_e0[t], e1 = g_e1[t];
    int p0 = 0, p1 = 0;
#pragma unroll
    for (int e = 0; e < EE; e++) {
        unsigned m0 = __ballot_sync(0xffffffffu, e0 == e);
        unsigned m1 = __ballot_sync(0xffffffffu, e1 == e);
        int cnt = __popc(m0) + __popc(m1);
        if (cnt == 0) continue;                 // uniform across warp
        int leader = __ffs(m0 | m1) - 1;
        int base = 0;
        if (lane == leader) base = atomicAdd(&g_cursor[e], cnt);
        base = __shfl_sync(0xffffffffu, base, leader);
        if (e0 == e) p0 = base + __popc(m0 & ltmask);
        if (e1 == e) p1 = base + __popc(m0) + __popc(m1 & ltmask);
    }
    g_slot_token[p0] = t; g_slot_w[p0] = g_w0t[t];
    g_slot_token[p1] = t; g_slot_w[p1] = g_w1t[t];
}

// ---------------------------------------------------------------------------
// Weight converter (fp32 -> fp16)
// ---------------------------------------------------------------------------
__global__ void k_convert_w(const float* __restrict__ W1,
                            const float* __restrict__ W2) {
    size_t i = ((size_t)blockIdx.x * 256 + threadIdx.x) * 4;
    const size_t W1N = (size_t)EE * DD * FF;
    const float* src; __half* dst; size_t j;
    if (i < W1N) { src = W1; j = i;        dst = g_W1; }
    else         { src = W2; j = i - W1N;  dst = g_W2; }
    float4 v = *reinterpret_cast<const float4*>(src + j);
    __half2 a; a.x = __float2half_rn(v.x); a.y = __float2half_rn(v.y);
    __half2 b; b.x = __float2half_rn(v.z); b.y = __float2half_rn(v.w);
    *reinterpret_cast<__half2*>(dst + j)     = a;
    *reinterpret_cast<__half2*>(dst + j + 2) = b;
}

__global__ void k_zero(float* __restrict__ out) {
    size_t i = ((size_t)blockIdx.x * 256 + threadIdx.x) * 4;
    *reinterpret_cast<float4*>(out + i) = make_float4(0.f, 0.f, 0.f, 0.f);
}

// ---------------------------------------------------------------------------
// Grouped GEMM (round-11 winner config, verbatim).
// MODE 0: H = relu(Xg @ W1[e] + b1[e]) -> fp16 scratch
// MODE 1: out[token] += w * (H @ W2[e] + b2[e])  (hidden REDG atomics)
// Tile: BM=128, BN=128, BK=64. 256 threads = 8 warps (4m x 2n), warp 32x64.
// blockIdx.x = N-block (fast), blockIdx.y = M-tile (A rows shared via L2).
// 3-stage cp.async pipeline (stage = iter % 3), ONE __syncthreads per k-iter,
// 2 CTAs/SM. XOR swizzle on 16B chunks -> conflict-free ldmatrix.
// ---------------------------------------------------------------------------
constexpr int SMEM_BYTES = 3 * (16384 + 16384);   // 96KB

template <int MODE>
__global__ void __launch_bounds__(256, 2) k_gemm(
    const float* __restrict__ bias, float* __restrict__ out) {
    constexpr int KDIM = MODE ? FF : DD;
    constexpr int NDIM = MODE ? DD : FF;
    constexpr int KT   = KDIM / 64;

    const int bid = blockIdx.y;           // M-tile (slow axis)
    if (bid >= g_num_tiles) return;
    const int e       = g_tile_e[bid];
    const int row0    = g_tile_r0[bid];
    const int seg_end = g_offsets[e + 1];
    const int n0      = blockIdx.x * 128; // N-block (fast axis)

    extern __shared__ char smem[];
    const uint32_t sA0 = smem_u32(smem);          // 3 x 16KB
    const uint32_t sB0 = sA0 + 3 * 16384;         // 3 x 16KB

    const int tid = threadIdx.x;
    const int lane = tid & 31, wid = tid >> 5;
    const int wm = wid >> 1, wn = wid & 1;        // 4m x 2n

    const __half* A = MODE ? g_H  : g_X;
    const __half* B = MODE ? g_W2 : g_W1;

    // Hoisted A-row bases (rows handled by this thread are k-invariant)
    size_t abase[4];
    bool   avalid[4];
#pragma unroll
    for (int i = 0; i < 4; i++) {
        int row = (tid + i * 256) >> 3;
        int rg  = row0 + row;
        avalid[i] = rg < seg_end;
        if (MODE == 0) {
            int tok = avalid[i] ? g_slot_token[rg] : 0;
            abase[i] = (size_t)tok * DD;
        } else {
            abase[i] = (size_t)(avalid[i] ? rg : 0) * FF;
        }
    }

    auto load_stage = [&](int ko, int st) {
        const int k0 = ko * 64;
        // A: 128 rows x 8 chunks of 16B (128B/row) = 1024 chunks, 4/thread
#pragma unroll
        for (int i = 0; i < 4; i++) {
            int c    = tid + i * 256;
            int row  = c >> 3;
            int kc   = c & 7;
            int phys = (kc ^ row) & 7;
            uint32_t s = sA0 + st * 16384 + row * 128 + phys * 16;
            cp16(s, A + abase[i] + k0 + (kc << 3), avalid[i]);
        }
        // B: 64 k-rows x 16 chunks (128 fp16 = 256B/row) = 1024 chunks, 4/thread
#pragma unroll
        for (int i = 0; i < 4; i++) {
            int c    = tid + i * 256;
            int kr   = c >> 4;
            int nc   = c & 15;
            int phys = (nc & 8) | ((nc ^ kr) & 7);
            uint32_t s = sB0 + st * 16384 + kr * 256 + phys * 16;
            size_t bidx = (size_t)e * KDIM * NDIM + (size_t)(k0 + kr) * NDIM
                        + n0 + (nc << 3);
            cp16(s, B + bidx, true);
        }
        cp_commit();
    };

    float acc[2][8][4];
#pragma unroll
    for (int a = 0; a < 2; a++)
#pragma unroll
        for (int b = 0; b < 8; b++)
#pragma unroll
            for (int c = 0; c < 4; c++) acc[a][b][c] = 0.f;

    load_stage(0, 0);
    load_stage(1, 1);
    int st = 0;
    for (int ko = 0; ko < KT; ko++) {
        cp_wait1();          // stage ko resident (<=1 group outstanding)
        __syncthreads();     // all warps done with slot (ko-1)%3 too

        int ld = ko + 2;
        if (ld < KT) load_stage(ld, ld % 3);
        else cp_commit();    // empty group keeps wait_group(1) accounting

#pragma unroll
        for (int ks = 0; ks < 4; ks++) {
            uint32_t af[2][4];
#pragma unroll
            for (int mt = 0; mt < 2; mt++) {
                int r  = wm * 32 + mt * 16 + (lane & 15);
                int kc = ks * 2 + (lane >> 4);
                int ph = (kc ^ r) & 7;
                ldsm_x4(af[mt], sA0 + st * 16384 + r * 128 + ph * 16);
            }
            uint32_t bf[16];
#pragma unroll
            for (int g = 0; g < 4; g++) {
                int kr = ks * 16 + (lane & 15);
                int nc = wn * 8 + g * 2 + (lane >> 4);
                int ph = (nc & 8) | ((nc ^ kr) & 7);
                ldsm_x4_t(&bf[g * 4], sB0 + st * 16384 + kr * 256 + ph * 16);
            }
#pragma unroll
            for (int mt = 0; mt < 2; mt++)
#pragma unroll
                for (int nt = 0; nt < 8; nt++) {
                    int idx = (nt >> 1) * 4 + (nt & 1) * 2;
                    mma_f16(acc[mt][nt], af[mt], bf[idx], bf[idx + 1]);
                }
        }
        st = (st == 2) ? 0 : st + 1;
    }

    // Epilogue
#pragma unroll
    for (int mt = 0; mt < 2; mt++) {
        int rr = wm * 32 + mt * 16 + (lane >> 2);
#pragma unroll
        for (int i = 0; i < 2; i++) {
            int rg = row0 + rr + i * 8;
            if (rg < seg_end) {
                if (MODE == 0) {
                    size_t base = (size_t)rg * FF;
#pragma unroll
                    for (int nt = 0; nt < 8; nt++) {
                        int col = n0 + wn * 64 + nt * 8 + ((lane & 3) << 1);
                        float v0 = acc[mt][nt][i * 2 + 0] + bias[e * NDIM + col];
                        float v1 = acc[mt][nt][i * 2 + 1] + bias[e * NDIM + col + 1];
                        __half2 hp;
                        hp.x = __float2half_rn(fmaxf(v0, 0.f));
                        hp.y = __float2half_rn(fmaxf(v1, 0.f));
                        *reinterpret_cast<__half2*>(g_H + base + col) = hp;
                    }
                } else {
                    int tok = g_slot_token[rg];
                    float w = g_slot_w[rg];
                    float* orow = out + (size_t)tok * DD;
#pragma unroll
                    for (int nt = 0; nt < 8; nt++) {
                        int col = n0 + wn * 64 + nt * 8 + ((lane & 3) << 1);
                        float v0 = (acc[mt][nt][i * 2 + 0] + bias[e * NDIM + col]) * w;
                        float v1 = (acc[mt][nt][i * 2 + 1] + bias[e * NDIM + col + 1]) * w;
                        atomicAdd(orow + col, v0);
                        atomicAdd(orow + col + 1, v1);
                    }
                }
            }
        }
    }
}

// ---------------------------------------------------------------------------
// Launch. Stream fork-join (capture-legal): convert_w runs concurrently with
// router->scan->scatter; k_zero runs concurrently with GEMM1. Streams/events
// are host-side resources created once (no device memory).
// ---------------------------------------------------------------------------
extern "C" void kernel_launch(void* const* d_in, const int* in_sizes, int n_in,
                              void* d_out, int out_size) {
    const float* x  = (const float*)d_in[0];
    const float* Wr = (const float*)d_in[1];
    const float* br = (const float*)d_in[2];
    const float* W1 = (const float*)d_in[3];
    const float* b1 = (const float*)d_in[4];
    const float* W2 = (const float*)d_in[5];
    const float* b2 = (const float*)d_in[6];
    float* out = (float*)d_out;

    static cudaStream_t sW = nullptr, sZ = nullptr;
    static cudaEvent_t evRoot = nullptr, evW = nullptr, evZ = nullptr;
    if (sW == nullptr) {
        cudaStreamCreateWithFlags(&sW, cudaStreamNonBlocking);
        cudaStreamCreateWithFlags(&sZ, cudaStreamNonBlocking);
        cudaEventCreateWithFlags(&evRoot, cudaEventDisableTiming);
        cudaEventCreateWithFlags(&evW,    cudaEventDisableTiming);
        cudaEventCreateWithFlags(&evZ,    cudaEventDisableTiming);
        cudaFuncSetAttribute(k_gemm<0>,
            cudaFuncAttributeMaxDynamicSharedMemorySize, SMEM_BYTES);
        cudaFuncSetAttribute(k_gemm<1>,
            cudaFuncAttributeMaxDynamicSharedMemorySize, SMEM_BYTES);
    }

    // Fork side streams off the main (capture) stream.
    cudaEventRecord(evRoot, 0);
    cudaStreamWaitEvent(sW, evRoot, 0);
    cudaStreamWaitEvent(sZ, evRoot, 0);

    // Side stream W: weight conversion (independent of router chain).
    k_convert_w<<<(2 * EE * DD * FF / 4) / 256, 256, 0, sW>>>(W1, W2);
    cudaEventRecord(evW, sW);

    // Side stream Z: zero the output (only needed before GEMM2).
    k_zero<<<(TT * DD / 4) / 256, 256, 0, sZ>>>(out);
    cudaEventRecord(evZ, sZ);

    // Main stream: routing chain.
    k_router<<<TT / 8, 256>>>(x, Wr, br);
    k_scan<<<1, 1>>>();
    k_scatter<<<TT / 256, 256>>>();

    // Join W before GEMM1 (needs g_W1).
    cudaStreamWaitEvent(0, evW, 0);
    // GEMM1: 65536 x 2048, K=512 (grouped by expert)
    k_gemm<0><<<dim3(FF / 128, 520), 256, SMEM_BYTES>>>(b1, nullptr);

    // Join Z before GEMM2 (accumulates into out).
    cudaStreamWaitEvent(0, evZ, 0);
    // GEMM2: 65536 x 512, K=2048 (grouped), hidden REDG atomics
    k_gemm<1><<<dim3(DD / 128, 520), 256, SMEM_BYTES>>>(b2, out);
}

// round 17
// speedup vs baseline: 1.0953x; 1.0026x over previous
#include <cuda_runtime.h>
#include <cuda_fp16.h>
#include <cstdint>
#include <cstddef>

// Problem constants
#define TT 32768      // tokens (B*S)
#define DD 512        // model dim
#define FF 2048       // ffn dim
#define EE 8          // experts
#define SLOTS 65536   // TT * K(=2)

// ---------------------------------------------------------------------------
// Device scratch (allocation-free rule: __device__ globals).
// Referenced ONLY from device code (host use would hit ATS host-shadow zeros).
// ---------------------------------------------------------------------------
__device__ __align__(256) int   g_e0[TT], g_e1[TT];
__device__ __align__(256) float g_w0t[TT], g_w1t[TT];
__device__ __align__(256) int   g_counts[EE];
__device__ __align__(256) int   g_offsets[EE + 1];
__device__ __align__(256) int   g_cursor[EE];
__device__ __align__(256) int   g_tile_e[528], g_tile_r0[528];
__device__ __align__(256) int   g_num_tiles;
__device__ __align__(256) int   g_slot_token[SLOTS];
__device__ __align__(256) float g_slot_w[SLOTS];

// fp16 operand scratch (single precision operands; fp32 accumulate in MMA)
__device__ __align__(256) __half g_X [(size_t)TT * DD];
__device__ __align__(256) __half g_W1[(size_t)EE * DD * FF];
__device__ __align__(256) __half g_W2[(size_t)EE * FF * DD];
__device__ __align__(256) __half g_H [(size_t)SLOTS * FF];

// ---------------------------------------------------------------------------
// PTX helpers
// ---------------------------------------------------------------------------
__device__ __forceinline__ uint32_t smem_u32(const void* p) {
    uint32_t a;
    asm("{ .reg .u64 t; cvta.to.shared.u64 t, %1; cvt.u32.u64 %0, t; }"
        : "=r"(a) : "l"(p));
    return a;
}

__device__ __forceinline__ void cp16(uint32_t s, const void* g, bool valid) {
    int sz = valid ? 16 : 0;
    asm volatile("cp.async.cg.shared.global [%0], [%1], 16, %2;\n"
                 :: "r"(s), "l"(__cvta_generic_to_global(g)), "r"(sz));
}
__device__ __forceinline__ void cp_commit() {
    asm volatile("cp.async.commit_group;\n" ::);
}
__device__ __forceinline__ void cp_wait1() {
    asm volatile("cp.async.wait_group 1;\n" ::);
}

__device__ __forceinline__ void ldsm_x4(uint32_t* r, uint32_t addr) {
    asm volatile("ldmatrix.sync.aligned.m8n8.x4.shared.b16 {%0,%1,%2,%3}, [%4];"
                 : "=r"(r[0]), "=r"(r[1]), "=r"(r[2]), "=r"(r[3]) : "r"(addr));
}
__device__ __forceinline__ void ldsm_x4_t(uint32_t* r, uint32_t addr) {
    asm volatile("ldmatrix.sync.aligned.m8n8.x4.trans.shared.b16 {%0,%1,%2,%3}, [%4];"
                 : "=r"(r[0]), "=r"(r[1]), "=r"(r[2]), "=r"(r[3]) : "r"(addr));
}

__device__ __forceinline__ void mma_f16(float* d, const uint32_t* a,
                                        uint32_t b0, uint32_t b1) {
    asm volatile(
        "mma.sync.aligned.m16n8k16.row.col.f32.f16.f16.f32 "
        "{%0,%1,%2,%3}, {%4,%5,%6,%7}, {%8,%9}, {%0,%1,%2,%3};\n"
        : "+f"(d[0]), "+f"(d[1]), "+f"(d[2]), "+f"(d[3])
        : "r"(a[0]), "r"(a[1]), "r"(a[2]), "r"(a[3]), "r"(b0), "r"(b1));
}

// ---------------------------------------------------------------------------
// Router (+ fused x->fp16 convert): logits = x @ Wr + br ; top-2 ;
// renormalized softmax weights. Each block also converts its own 8 rows of x.
// ---------------------------------------------------------------------------
__global__ void k_router(const float* __restrict__ x,
                         const float* __restrict__ Wr,
                         const float* __restrict__ br) {
    __shared__ float sW[EE * DD];   // transposed: sW[e*512 + d]
    __shared__ float sbr[EE];
    const int tid = threadIdx.x;

    // Fused convert: this block's 8 token rows = 4096 floats = 1024 float4
    {
        size_t base = (size_t)blockIdx.x * 8 * DD;
#pragma unroll
        for (int k = 0; k < 4; k++) {
            size_t i = base + (size_t)(tid + k * 256) * 4;
            float4 v = *reinterpret_cast<const float4*>(x + i);
            __half2 a; a.x = __float2half_rn(v.x); a.y = __float2half_rn(v.y);
            __half2 b; b.x = __float2half_rn(v.z); b.y = __float2half_rn(v.w);
            *reinterpret_cast<__half2*>(g_X + i)     = a;
            *reinterpret_cast<__half2*>(g_X + i + 2) = b;
        }
    }

    for (int i = tid; i < EE * DD; i += 256) {
        int e = i >> 9, d = i & 511;
        sW[i] = Wr[d * EE + e];
    }
    if (tid < EE) sbr[tid] = br[tid];
    __syncthreads();

    const int lane = tid & 31, wid = tid >> 5;
    const int t = blockIdx.x * 8 + wid;
    const float* xr = x + (size_t)t * DD;

    float a[EE];
#pragma unroll
    for (int e = 0; e < EE; e++) a[e] = 0.f;
#pragma unroll
    for (int i = 0; i < 16; i++) {
        float xv = xr[lane + 32 * i];
#pragma unroll
        for (int e = 0; e < EE; e++) a[e] += xv * sW[e * DD + lane + 32 * i];
    }
#pragma unroll
    for (int off = 16; off > 0; off >>= 1) {
#pragma unroll
        for (int e = 0; e < EE; e++)
            a[e] += __shfl_down_sync(0xffffffffu, a[e], off);
    }
    if (lane == 0) {
#pragma unroll
        for (int e = 0; e < EE; e++) a[e] += sbr[e];
        int e0 = 0; float m0 = a[0];
#pragma unroll
        for (int e = 1; e < EE; e++) if (a[e] > m0) { m0 = a[e]; e0 = e; }
        int e1 = -1; float m1 = -1e30f;
#pragma unroll
        for (int e = 0; e < EE; e++)
            if (e != e0 && a[e] > m1) { m1 = a[e]; e1 = e; }
        float d  = expf(m1 - m0);           // m1 <= m0
        float w0 = 1.f / (1.f + d);
        float w1 = d * w0;
        g_e0[t] = e0; g_e1[t] = e1;
        g_w0t[t] = w0; g_w1t[t] = w1;
        atomicAdd(&g_counts[e0], 1);
        atomicAdd(&g_counts[e1], 1);
    }
}

// ---------------------------------------------------------------------------
// Scan (parallelized): thread 0 does the tiny prefix sums; 256 threads fill
// the tile table in parallel. (Was a serial <<<1,1>>> loop: 8.4us measured.)
// ---------------------------------------------------------------------------
__global__ void k_scan() {
    __shared__ int s_off[EE];      // expert slot offsets
    __shared__ int s_tbase[EE];    // expert tile-table base
    __shared__ int s_ntile[EE];    // tiles per expert
    const int tid = threadIdx.x;

    if (tid == 0) {
        int off = 0, tb = 0;
        for (int e = 0; e < EE; e++) {
            int cnt = g_counts[e];
            g_offsets[e] = off;
            g_cursor[e]  = off;
            s_off[e]     = off;
            int nt = (cnt + 127) >> 7;
            s_tbase[e]   = tb;
            s_ntile[e]   = nt;
            off += cnt;
            tb  += nt;
            g_counts[e] = 0;
        }
        g_offsets[EE] = off;   // == SLOTS
        g_num_tiles = tb;
    }
    __syncthreads();

    // Parallel tile-table fill: entry (e, t) -> index s_tbase[e] + t
#pragma unroll
    for (int e = 0; e < EE; e++) {
        int nt = s_ntile[e];
        for (int t = tid; t < nt; t += 256) {
            int idx = s_tbase[e] + t;
            g_tile_e[idx]  = e;
            g_tile_r0[idx] = s_off[e] + t * 128;
        }
    }
}

// Warp-aggregated scatter: one atomic per (warp, expert) instead of per token.
__global__ void k_scatter() {
    const int t = blockIdx.x * 256 + threadIdx.x;
    const int lane = threadIdx.x & 31;
    const unsigned ltmask = (1u << lane) - 1u;
    const int e0 = g_e0[t], e1 = g_e1[t];
    int p0 = 0, p1 = 0;
#pragma unroll
    for (int e = 0; e < EE; e++) {
        unsigned m0 = __ballot_sync(0xffffffffu, e0 == e);
        unsigned m1 = __ballot_sync(0xffffffffu, e1 == e);
        int cnt = __popc(m0) + __popc(m1);
        if (cnt == 0) continue;                 // uniform across warp
        int leader = __ffs(m0 | m1) - 1;
        int base = 0;
        if (lane == leader) base = atomicAdd(&g_cursor[e], cnt);
        base = __shfl_sync(0xffffffffu, base, leader);
        if (e0 == e) p0 = base + __popc(m0 & ltmask);
        if (e1 == e) p1 = base + __popc(m0) + __popc(m1 & ltmask);
    }
    g_slot_token[p0] = t; g_slot_w[p0] = g_w0t[t];
    g_slot_token[p1] = t; g_slot_w[p1] = g_w1t[t];
}

// ---------------------------------------------------------------------------
// Weight converter (fp32 -> fp16)
// ---------------------------------------------------------------------------
__global__ void k_convert_w(const float* __restrict__ W1,
                            const float* __restrict__ W2) {
    size_t i = ((size_t)blockIdx.x * 256 + threadIdx.x) * 4;
    const size_t W1N = (size_t)EE * DD * FF;
    const float* src; __half* dst; size_t j;
    if (i < W1N) { src = W1; j = i;        dst = g_W1; }
    else         { src = W2; j = i - W1N;  dst = g_W2; }
    float4 v = *reinterpret_cast<const float4*>(src + j);
    __half2 a; a.x = __float2half_rn(v.x); a.y = __float2half_rn(v.y);
    __half2 b; b.x = __float2half_rn(v.z); b.y = __float2half_rn(v.w);
    *reinterpret_cast<__half2*>(dst + j)     = a;
    *reinterpret_cast<__half2*>(dst + j + 2) = b;
}

__global__ void k_zero(float* __restrict__ out) {
    size_t i = ((size_t)blockIdx.x * 256 + threadIdx.x) * 4;
    *reinterpret_cast<float4*>(out + i) = make_float4(0.f, 0.f, 0.f, 0.f);
}

// ---------------------------------------------------------------------------
// Grouped GEMM (round-11 winner config, verbatim).
// MODE 0: H = relu(Xg @ W1[e] + b1[e]) -> fp16 scratch
// MODE 1: out[token] += w * (H @ W2[e] + b2[e])  (hidden REDG atomics)
// Tile: BM=128, BN=128, BK=64. 256 threads = 8 warps (4m x 2n), warp 32x64.
// blockIdx.x = N-block (fast), blockIdx.y = M-tile (A rows shared via L2).
// 3-stage cp.async pipeline (stage = iter % 3), ONE __syncthreads per k-iter,
// 2 CTAs/SM. XOR swizzle on 16B chunks -> conflict-free ldmatrix.
// ---------------------------------------------------------------------------
constexpr int SMEM_BYTES = 3 * (16384 + 16384);   // 96KB

template <int MODE>
__global__ void __launch_bounds__(256, 2) k_gemm(
    const float* __restrict__ bias, float* __restrict__ out) {
    constexpr int KDIM = MODE ? FF : DD;
    constexpr int NDIM = MODE ? DD : FF;
    constexpr int KT   = KDIM / 64;

    const int bid = blockIdx.y;           // M-tile (slow axis)
    if (bid >= g_num_tiles) return;
    const int e       = g_tile_e[bid];
    const int row0    = g_tile_r0[bid];
    const int seg_end = g_offsets[e + 1];
    const int n0      = blockIdx.x * 128; // N-block (fast axis)

    extern __shared__ char smem[];
    const uint32_t sA0 = smem_u32(smem);          // 3 x 16KB
    const uint32_t sB0 = sA0 + 3 * 16384;         // 3 x 16KB

    const int tid = threadIdx.x;
    const int lane = tid & 31, wid = tid >> 5;
    const int wm = wid >> 1, wn = wid & 1;        // 4m x 2n

    const __half* A = MODE ? g_H  : g_X;
    const __half* B = MODE ? g_W2 : g_W1;

    // Hoisted A-row bases (rows handled by this thread are k-invariant)
    size_t abase[4];
    bool   avalid[4];
#pragma unroll
    for (int i = 0; i < 4; i++) {
        int row = (tid + i * 256) >> 3;
        int rg  = row0 + row;
        avalid[i] = rg < seg_end;
        if (MODE == 0) {
            int tok = avalid[i] ? g_slot_token[rg] : 0;
            abase[i] = (size_t)tok * DD;
        } else {
            abase[i] = (size_t)(avalid[i] ? rg : 0) * FF;
        }
    }

    auto load_stage = [&](int ko, int st) {
        const int k0 = ko * 64;
        // A: 128 rows x 8 chunks of 16B (128B/row) = 1024 chunks, 4/thread
#pragma unroll
        for (int i = 0; i < 4; i++) {
            int c    = tid + i * 256;
            int row  = c >> 3;
            int kc   = c & 7;
            int phys = (kc ^ row) & 7;
            uint32_t s = sA0 + st * 16384 + row * 128 + phys * 16;
            cp16(s, A + abase[i] + k0 + (kc << 3), avalid[i]);
        }
        // B: 64 k-rows x 16 chunks (128 fp16 = 256B/row) = 1024 chunks, 4/thread
#pragma unroll
        for (int i = 0; i < 4; i++) {
            int c    = tid + i * 256;
            int kr   = c >> 4;
            int nc   = c & 15;
            int phys = (nc & 8) | ((nc ^ kr) & 7);
            uint32_t s = sB0 + st * 16384 + kr * 256 + phys * 16;
            size_t bidx = (size_t)e * KDIM * NDIM + (size_t)(k0 + kr) * NDIM
                        + n0 + (nc << 3);
            cp16(s, B + bidx, true);
        }
        cp_commit();
    };

    float acc[2][8][4];
#pragma unroll
    for (int a = 0; a < 2; a++)
#pragma unroll
        for (int b = 0; b < 8; b++)
#pragma unroll
            for (int c = 0; c < 4; c++) acc[a][b][c] = 0.f;

    load_stage(0, 0);
    load_stage(1, 1);
    int st = 0;
    for (int ko = 0; ko < KT; ko++) {
        cp_wait1();          // stage ko resident (<=1 group outstanding)
        __syncthreads();     // all warps done with slot (ko-1)%3 too

        int ld = ko + 2;
        if (ld < KT) load_stage(ld, ld % 3);
        else cp_commit();    // empty group keeps wait_group(1) accounting

#pragma unroll
        for (int ks = 0; ks < 4; ks++) {
            uint32_t af[2][4];
#pragma unroll
            for (int mt = 0; mt < 2; mt++) {
                int r  = wm * 32 + mt * 16 + (lane & 15);
                int kc = ks * 2 + (lane >> 4);
                int ph = (kc ^ r) & 7;
                ldsm_x4(af[mt], sA0 + st * 16384 + r * 128 + ph * 16);
            }
            uint32_t bf[16];
#pragma unroll
            for (int g = 0; g < 4; g++) {
                int kr = ks * 16 + (lane & 15);
                int nc = wn * 8 + g * 2 + (lane >> 4);
                int ph = (nc & 8) | ((nc ^ kr) & 7);
                ldsm_x4_t(&bf[g * 4], sB0 + st * 16384 + kr * 256 + ph * 16);
            }
#pragma unroll
            for (int mt = 0; mt < 2; mt++)
#pragma unroll
                for (int nt = 0; nt < 8; nt++) {
                    int idx = (nt >> 1) * 4 + (nt & 1) * 2;
                    mma_f16(acc[mt][nt], af[mt], bf[idx], bf[idx + 1]);
                }
        }
        st = (st == 2) ? 0 : st + 1;
    }

    // Epilogue
#pragma unroll
    for (int mt = 0; mt < 2; mt++) {
        int rr = wm * 32 + mt * 16 + (lane >> 2);
#pragma unroll
        for (int i = 0; i < 2; i++) {
            int rg = row0 + rr + i * 8;
            if (rg < seg_end) {
                if (MODE == 0) {
                    size_t base = (size_t)rg * FF;
#pragma unroll
                    for (int nt = 0; nt < 8; nt++) {
                        int col = n0 + wn * 64 + nt * 8 + ((lane & 3) << 1);
                        float v0 = acc[mt][nt][i * 2 + 0] + bias[e * NDIM + col];
                        float v1 = acc[mt][nt][i * 2 + 1] + bias[e * NDIM + col + 1];
                        __half2 hp;
                        hp.x = __float2half_rn(fmaxf(v0, 0.f));
                        hp.y = __float2half_rn(fmaxf(v1, 0.f));
                        *reinterpret_cast<__half2*>(g_H + base + col) = hp;
                    }
                } else {
                    int tok = g_slot_token[rg];
                    float w = g_slot_w[rg];
                    float* orow = out + (size_t)tok * DD;
#pragma unroll
                    for (int nt = 0; nt < 8; nt++) {
                        int col = n0 + wn * 64 + nt * 8 + ((lane & 3) << 1);
                        float v0 = (acc[mt][nt][i * 2 + 0] + bias[e * NDIM + col]) * w;
                        float v1 = (acc[mt][nt][i * 2 + 1] + bias[e * NDIM + col + 1]) * w;
                        atomicAdd(orow + col, v0);
                        atomicAdd(orow + col + 1, v1);
                    }
                }
            }
        }
    }
}

// ---------------------------------------------------------------------------
// Launch. Stream fork-join (capture-legal): convert_w runs concurrently with
// router->scan->scatter; k_zero runs concurrently with GEMM1. Streams/events
// are host-side resources created once (no device memory).
// ---------------------------------------------------------------------------
extern "C" void kernel_launch(void* const* d_in, const int* in_sizes, int n_in,
                              void* d_out, int out_size) {
    const float* x  = (const float*)d_in[0];
    const float* Wr = (const float*)d_in[1];
    const float* br = (const float*)d_in[2];
    const float* W1 = (const float*)d_in[3];
    const float* b1 = (const float*)d_in[4];
    const float* W2 = (const float*)d_in[5];
    const float* b2 = (const float*)d_in[6];
    float* out = (float*)d_out;

    static cudaStream_t sW = nullptr, sZ = nullptr;
    static cudaEvent_t evRoot = nullptr, evW = nullptr, evZ = nullptr;
    if (sW == nullptr) {
        cudaStreamCreateWithFlags(&sW, cudaStreamNonBlocking);
        cudaStreamCreateWithFlags(&sZ, cudaStreamNonBlocking);
        cudaEventCreateWithFlags(&evRoot, cudaEventDisableTiming);
        cudaEventCreateWithFlags(&evW,    cudaEventDisableTiming);
        cudaEventCreateWithFlags(&evZ,    cudaEventDisableTiming);
        cudaFuncSetAttribute(k_gemm<0>,
            cudaFuncAttributeMaxDynamicSharedMemorySize, SMEM_BYTES);
        cudaFuncSetAttribute(k_gemm<1>,
            cudaFuncAttributeMaxDynamicSharedMemorySize, SMEM_BYTES);
    }

    // Fork side streams off the main (capture) stream.
    cudaEventRecord(evRoot, 0);
    cudaStreamWaitEvent(sW, evRoot, 0);
    cudaStreamWaitEvent(sZ, evRoot, 0);

    // Side stream W: weight conversion (independent of router chain).
    k_convert_w<<<(2 * EE * DD * FF / 4) / 256, 256, 0, sW>>>(W1, W2);
    cudaEventRecord(evW, sW);

    // Side stream Z: zero the output (only needed before GEMM2).
    k_zero<<<(TT * DD / 4) / 256, 256, 0, sZ>>>(out);
    cudaEventRecord(evZ, sZ);

    // Main stream: routing chain.
    k_router<<<TT / 8, 256>>>(x, Wr, br);
    k_scan<<<1, 256>>>();
    k_scatter<<<TT / 256, 256>>>();

    // Join W before GEMM1 (needs g_W1).
    cudaStreamWaitEvent(0, evW, 0);
    // GEMM1: 65536 x 2048, K=512 (grouped by expert)
    k_gemm<0><<<dim3(FF / 128, 520), 256, SMEM_BYTES>>>(b1, nullptr);

    // Join Z before GEMM2 (accumulates into out).
    cudaStreamWaitEvent(0, evZ, 0);
    // GEMM2: 65536 x 512, K=2048 (grouped), hidden REDG atomics
    k_gemm<1><<<dim3(DD / 128, 520), 256, SMEM_BYTES>>>(b2, out);
}